// round 16
// baseline (speedup 1.0000x reference)
#include <cuda_runtime.h>
#include <cuda_fp16.h>
#include <cuda_pipeline.h>
#include <mma.h>
#include <cstdint>

using namespace nvcuda;

// Problem constants
#define BATCH   512
#define IN_DIM  256
#define OUT_DIM 256
#define NROWS   68          // G + K (rows 0..66 spline, 67 silu)
#define CG      16          // channels per block (8 pairs)
#define NITER   8           // channel pairs
#define KD2     144         // 2*68 = 136 padded to 144 (9 x 16)
#define MT      128         // M tile (batch)
#define NTILE   128         // N tile (outputs)
#define ZSPLIT  (IN_DIM / CG)   // 16
#define NTHREADS 256

// fp16 W copy: [k, c, n] layout, as 16B chunks (8 halfs). 8.9 MB.
#define WH_CHUNKS (NROWS * IN_DIM * OUT_DIM / 8)   // 557056
__device__ uint4 g_wh[WH_CHUNKS];

// smem (halfs, padded for conflict-free LDSM), DOUBLE buffered
#define A_STRIDE 152                         // 304B rows
#define B_STRIDE 136                         // 272B rows (17 x 16B)
#define A_BYTES  (MT * A_STRIDE * 2)         // 38912
#define B_BYTES  (KD2 * B_STRIDE * 2)        // 39168
#define SMEM_TOTAL (2 * A_BYTES + 2 * B_BYTES)   // 156160 (epilogue reuses)

// ---------------- convert w to fp16 ----------------
__global__ void __launch_bounds__(256, 8)
convert_w_kernel(const float* __restrict__ w)
{
    int i = blockIdx.x * 256 + threadIdx.x;
    const float4* src = (const float4*)w + (size_t)i * 2;
    float4 a = src[0];
    float4 b = src[1];
    __half2 h0 = __floats2half2_rn(a.x, a.y);
    __half2 h1 = __floats2half2_rn(a.z, a.w);
    __half2 h2 = __floats2half2_rn(b.x, b.y);
    __half2 h3 = __floats2half2_rn(b.z, b.w);
    uint4 o;
    o.x = *(unsigned*)&h0; o.y = *(unsigned*)&h1;
    o.z = *(unsigned*)&h2; o.w = *(unsigned*)&h3;
    g_wh[i] = o;
}

// ---------------- zero output ----------------
__global__ void __launch_bounds__(256, 1)
zero_out_kernel(float4* __restrict__ out)
{
    out[blockIdx.x * 256 + threadIdx.x] = make_float4(0.f, 0.f, 0.f, 0.f);
}

// ---------------- basis + silu into A image ----------------
// t = [-1,-1,-1, linspace(-1,1,65), 1,1,1]; interior knots exact multiples of 2^-5.
__device__ __forceinline__ void gen_A(__half* arow, float xv, int* prevj)
{
    if (*prevj >= 0) {
        int pj = *prevj;
#pragma unroll
        for (int d = 0; d < 4; d++) arow[pj + d] = __ushort_as_half(0);
    }
    float f = (xv + 1.0f) * 32.0f;
    int j = (int)floorf(f);
    j = min(max(j, 0), 63);
    float tj  = -1.0f + (float)j * 0.03125f;
    float tj1 = -1.0f + (float)(j + 1) * 0.03125f;
    if (xv < tj) j--; else if (xv >= tj1) j++;
    j = min(max(j, 0), 63);

    float kn[6];
#pragma unroll
    for (int d = 0; d < 6; d++)
        kn[d] = -1.0f + (float)min(max(j + d - 2, 0), 64) * 0.03125f;

    float L1 = xv - kn[2], L2 = xv - kn[1], L3 = xv - kn[0];
    float R1 = kn[3] - xv, R2 = kn[4] - xv, R3 = kn[5] - xv;

    float temp, saved;
    temp = 1.0f / (R1 + L1);
    float n0 = R1 * temp;
    float n1 = L1 * temp;
    temp = n0 / (R1 + L2);
    float m0 = R1 * temp;  saved = L2 * temp;
    temp = n1 / (R2 + L1);
    float m1 = saved + R2 * temp;  float m2 = L1 * temp;
    temp = m0 / (R1 + L3);
    float q0 = R1 * temp;  saved = L3 * temp;
    temp = m1 / (R2 + L2);
    float q1 = saved + R2 * temp;  saved = L2 * temp;
    temp = m2 / (R3 + L1);
    float q2 = saved + R3 * temp;  float q3 = L1 * temp;

    float silu = xv / (1.0f + __expf(-xv));

    arow[j + 0] = __float2half_rn(q0);
    arow[j + 1] = __float2half_rn(q1);
    arow[j + 2] = __float2half_rn(q2);
    arow[j + 3] = __float2half_rn(q3);
    arow[67]    = __float2half_rn(silu);
    *prevj = j;
}

// ---------------- main kernel: paired channels, balanced producer,
//                  fused atomic epilogue (no scratch / reduce) ----------------
__global__ void __launch_bounds__(NTHREADS, 1)
kan_wmma_kernel(const float* __restrict__ x, float* __restrict__ out)
{
    extern __shared__ __align__(256) char smem[];
    __half* A[2] = { (__half*)smem, (__half*)(smem + A_BYTES) };
    __half* B[2] = { (__half*)(smem + 2 * A_BYTES),
                     (__half*)(smem + 2 * A_BYTES + B_BYTES) };

    const int tid = threadIdx.x;
    const int wid = tid >> 5;
    const int wm  = wid & 3;            // warp m: rows wm*32
    const int wn  = wid >> 2;           // warp n: cols wn*64
    const int b0  = blockIdx.x * MT;
    const int ny  = blockIdx.y;         // n-half
    const int c0  = blockIdx.z * CG;

    // producer assignment: every thread gens ONE (row, channel-slot) and loads B chunks
    const int gm = tid & 127;           // A row
    const int gc = tid >> 7;            // channel slot within pair (0/1)

    // zero all smem once (pads stay zero forever)
    {
        uint4 z = make_uint4(0, 0, 0, 0);
        uint4* p = (uint4*)smem;
        for (int j = tid; j < SMEM_TOTAL / 16; j += NTHREADS) p[j] = z;
    }
    __syncthreads();

    int prevj[2] = { -1, -1 };
    float xv = __ldg(x + (size_t)(b0 + gm) * IN_DIM + c0 + gc);

    // prologue: produce pair 0 into buffer 0 (gen + B chunks by ALL threads)
    {
        gen_A(A[0] + gm * A_STRIDE + gc * NROWS, xv, &prevj[0]);
        xv = __ldg(x + (size_t)(b0 + gm) * IN_DIM + c0 + 2 + gc);
        uint4* dst = (uint4*)B[0];
        for (int j = tid; j < 2 * NROWS * 16; j += NTHREADS) {
            int k2 = j >> 4;                 // image row 0..135
            int q  = j & 15;
            int ch = c0 + (k2 >= NROWS);
            int k  = (k2 >= NROWS) ? k2 - NROWS : k2;
            __pipeline_memcpy_async(dst + k2 * 17 + q,
                g_wh + ((size_t)(k * IN_DIM + ch) * 32) + ny * 16 + q, 16);
        }
        __pipeline_commit();
    }

    wmma::fragment<wmma::accumulator, 16, 16, 16, float> acc[2][4];
#pragma unroll
    for (int i = 0; i < 2; i++)
#pragma unroll
        for (int j = 0; j < 4; j++) wmma::fill_fragment(acc[i][j], 0.0f);

    for (int it = 0; it < NITER; it++) {
        // produce pair it+1 into the other buffer
        if (it + 1 < NITER) {
            const int nb = (it + 1) & 1;
            gen_A(A[nb] + gm * A_STRIDE + gc * NROWS, xv, &prevj[nb]);
            if (it + 2 < NITER)
                xv = __ldg(x + (size_t)(b0 + gm) * IN_DIM + c0 + 2 * (it + 2) + gc);
            const int cp = c0 + 2 * (it + 1);
            uint4* dst = (uint4*)B[nb];
            for (int j = tid; j < 2 * NROWS * 16; j += NTHREADS) {
                int k2 = j >> 4;
                int q  = j & 15;
                int ch = cp + (k2 >= NROWS);
                int k  = (k2 >= NROWS) ? k2 - NROWS : k2;
                __pipeline_memcpy_async(dst + k2 * 17 + q,
                    g_wh + ((size_t)(k * IN_DIM + ch) * 32) + ny * 16 + q, 16);
            }
            __pipeline_commit();
            __pipeline_wait_prior(1);        // pair it's B complete
        } else {
            __pipeline_wait_prior(0);
        }
        __syncthreads();                     // pair it fully produced

        const __half* Ab = A[it & 1];
        const __half* Bb = B[it & 1];
#pragma unroll
        for (int kk = 0; kk < KD2 / 16; kk++) {
            wmma::fragment<wmma::matrix_a, 16, 16, 16, __half, wmma::row_major> af[2];
            wmma::fragment<wmma::matrix_b, 16, 16, 16, __half, wmma::row_major> bf[4];
#pragma unroll
            for (int i = 0; i < 2; i++)
                wmma::load_matrix_sync(af[i],
                    Ab + (wm * 32 + i * 16) * A_STRIDE + kk * 16, A_STRIDE);
#pragma unroll
            for (int j = 0; j < 4; j++)
                wmma::load_matrix_sync(bf[j],
                    Bb + (kk * 16) * B_STRIDE + wn * 64 + j * 16, B_STRIDE);
#pragma unroll
            for (int i = 0; i < 2; i++)
#pragma unroll
                for (int j = 0; j < 4; j++)
                    wmma::mma_sync(acc[i][j], af[i], bf[j], acc[i][j]);
        }
        __syncthreads();                     // MMA(it) done before buf reuse
    }

    // epilogue: stage fp32 tile (128x128) in smem, then atomicAdd into out
    float* stage = (float*)smem;
#pragma unroll
    for (int i = 0; i < 2; i++)
#pragma unroll
        for (int j = 0; j < 4; j++)
            wmma::store_matrix_sync(
                stage + (wm * 32 + i * 16) * NTILE + wn * 64 + j * 16,
                acc[i][j], NTILE, wmma::mem_row_major);
    __syncthreads();

    {
        float* dstb = out + (size_t)b0 * OUT_DIM + ny * NTILE;
        const float4* st4 = (const float4*)stage;
#pragma unroll
        for (int r = 0; r < 16; r++) {
            int q  = r * NTHREADS + tid;      // float4 index in 128x128 tile
            int mm = q >> 5;
            int nn = q & 31;
            float4 v = st4[q];
            float* d = dstb + (size_t)mm * OUT_DIM + nn * 4;
            atomicAdd(d + 0, v.x);
            atomicAdd(d + 1, v.y);
            atomicAdd(d + 2, v.z);
            atomicAdd(d + 3, v.w);
        }
    }
}

extern "C" void kernel_launch(void* const* d_in, const int* in_sizes, int n_in,
                              void* d_out, int out_size)
{
    const float* x = (const float*)d_in[0];
    const float* w = (const float*)d_in[1];
    float* out = (float*)d_out;

    cudaFuncSetAttribute(kan_wmma_kernel,
                         cudaFuncAttributeMaxDynamicSharedMemorySize, SMEM_TOTAL);

    zero_out_kernel<<<(BATCH * OUT_DIM / 4) / 256, 256>>>((float4*)out);
    convert_w_kernel<<<WH_CHUNKS / 256, 256>>>(w);

    dim3 grid(BATCH / MT, OUT_DIM / NTILE, ZSPLIT);
    kan_wmma_kernel<<<grid, NTHREADS, SMEM_TOTAL>>>(x, out);
}

// round 17
// speedup vs baseline: 1.0468x; 1.0468x over previous
#include <cuda_runtime.h>
#include <cuda_fp16.h>
#include <mma.h>
#include <cstdint>

using namespace nvcuda;

// Problem constants
#define BATCH   512
#define IN_DIM  256
#define OUT_DIM 256
#define NROWS   68          // G + K (rows 0..66 spline, 67 silu)
#define CG      16          // channels per block (8 pairs)
#define NITER   8           // channel pairs
#define KD2     144         // 2*68 = 136 padded to 144 (9 x 16)
#define MT      128         // M tile (batch)
#define NTILE   128         // N tile (outputs)
#define ZSPLIT  (IN_DIM / CG)   // 16
#define NTHREADS 256
#define CHUNKS  (2 * NROWS * 16)   // 2176 16B fp16 chunks per B tile

// partial outputs: [z][b][n] fp32, 8 MB
__device__ float g_scratch[ZSPLIT * BATCH * OUT_DIM];

// smem (halfs, padded for conflict-free LDSM), DOUBLE buffered
#define A_STRIDE 152                         // 304B rows
#define B_STRIDE 136                         // 272B rows (17 x 16B)
#define A_BYTES  (MT * A_STRIDE * 2)         // 38912
#define B_BYTES  (KD2 * B_STRIDE * 2)        // 39168
#define SMEM_TOTAL (2 * A_BYTES + 2 * B_BYTES)   // 156160 (epilogue reuses)

// ---------------- basis + silu into A image ----------------
// t = [-1,-1,-1, linspace(-1,1,65), 1,1,1]; interior knots exact multiples of 2^-5.
__device__ __forceinline__ void gen_A(__half* arow, float xv, int* prevj)
{
    if (*prevj >= 0) {
        int pj = *prevj;
#pragma unroll
        for (int d = 0; d < 4; d++) arow[pj + d] = __ushort_as_half(0);
    }
    float f = (xv + 1.0f) * 32.0f;
    int j = (int)floorf(f);
    j = min(max(j, 0), 63);
    float tj  = -1.0f + (float)j * 0.03125f;
    float tj1 = -1.0f + (float)(j + 1) * 0.03125f;
    if (xv < tj) j--; else if (xv >= tj1) j++;
    j = min(max(j, 0), 63);

    float kn[6];
#pragma unroll
    for (int d = 0; d < 6; d++)
        kn[d] = -1.0f + (float)min(max(j + d - 2, 0), 64) * 0.03125f;

    float L1 = xv - kn[2], L2 = xv - kn[1], L3 = xv - kn[0];
    float R1 = kn[3] - xv, R2 = kn[4] - xv, R3 = kn[5] - xv;

    float temp, saved;
    temp = 1.0f / (R1 + L1);
    float n0 = R1 * temp;
    float n1 = L1 * temp;
    temp = n0 / (R1 + L2);
    float m0 = R1 * temp;  saved = L2 * temp;
    temp = n1 / (R2 + L1);
    float m1 = saved + R2 * temp;  float m2 = L1 * temp;
    temp = m0 / (R1 + L3);
    float q0 = R1 * temp;  saved = L3 * temp;
    temp = m1 / (R2 + L2);
    float q1 = saved + R2 * temp;  saved = L2 * temp;
    temp = m2 / (R3 + L1);
    float q2 = saved + R3 * temp;  float q3 = L1 * temp;

    float silu = xv / (1.0f + __expf(-xv));

    arow[j + 0] = __float2half_rn(q0);
    arow[j + 1] = __float2half_rn(q1);
    arow[j + 2] = __float2half_rn(q2);
    arow[j + 3] = __float2half_rn(q3);
    arow[67]    = __float2half_rn(silu);
    *prevj = j;
}

// chunk index -> fp32 w float4 pointer (2 consecutive float4 = 8 floats -> 8 halfs)
__device__ __forceinline__ const float4* chunk_src(const float* __restrict__ w,
                                                   int j, int cp, int ny)
{
    int k2 = j >> 4;                 // B image row 0..135
    int q  = j & 15;                 // 16B fp16 chunk within row
    int ch = cp + (k2 >= NROWS);
    int k  = (k2 >= NROWS) ? k2 - NROWS : k2;
    return (const float4*)w + ((size_t)(k * IN_DIM + ch) * 64 + ny * 32 + q * 2);
}

// cvt 2 float4 -> one uint4 of 8 halfs, store to B image chunk j
__device__ __forceinline__ void chunk_sts(__half* Bbuf, int j, float4 a, float4 b)
{
    int k2 = j >> 4, q = j & 15;
    __half2 h0 = __floats2half2_rn(a.x, a.y);
    __half2 h1 = __floats2half2_rn(a.z, a.w);
    __half2 h2 = __floats2half2_rn(b.x, b.y);
    __half2 h3 = __floats2half2_rn(b.z, b.w);
    uint4 o;
    o.x = *(unsigned*)&h0; o.y = *(unsigned*)&h1;
    o.z = *(unsigned*)&h2; o.w = *(unsigned*)&h3;
    *((uint4*)Bbuf + k2 * 17 + q) = o;
}

// ---------------- main kernel: fused fp32->fp16 B conversion, paired channels,
//                  balanced producer, LDG latency hidden behind MMA ------------
__global__ void __launch_bounds__(NTHREADS, 1)
kan_wmma_kernel(const float* __restrict__ x, const float* __restrict__ w)
{
    extern __shared__ __align__(256) char smem[];
    __half* A[2] = { (__half*)smem, (__half*)(smem + A_BYTES) };
    __half* B[2] = { (__half*)(smem + 2 * A_BYTES),
                     (__half*)(smem + 2 * A_BYTES + B_BYTES) };

    const int tid = threadIdx.x;
    const int wid = tid >> 5;
    const int wm  = wid & 3;            // warp m: rows wm*32
    const int wn  = wid >> 2;           // warp n: cols wn*64
    const int b0  = blockIdx.x * MT;
    const int ny  = blockIdx.y;         // n-half
    const int c0  = blockIdx.z * CG;

    const int gm = tid & 127;           // A row this thread generates
    const int gc = tid >> 7;            // channel slot within pair (0/1)

    // zero all smem once (pads stay zero forever)
    {
        uint4 z = make_uint4(0, 0, 0, 0);
        uint4* p = (uint4*)smem;
        for (int j = tid; j < SMEM_TOTAL / 16; j += NTHREADS) p[j] = z;
    }
    __syncthreads();

    int prevj[2] = { -1, -1 };
    float xv = __ldg(x + (size_t)(b0 + gm) * IN_DIM + c0 + gc);

    // prologue: produce pair 0 into buffer 0 (sync loads, one-time exposed stall)
    {
#pragma unroll
        for (int s = 0; s < 9; s++) {
            int j = tid + s * NTHREADS;
            if (j < CHUNKS) {
                const float4* s4 = chunk_src(w, j, c0, ny);
                float4 a = s4[0], b = s4[1];
                chunk_sts(B[0], j, a, b);
            }
        }
        gen_A(A[0] + gm * A_STRIDE + gc * NROWS, xv, &prevj[0]);
        xv = __ldg(x + (size_t)(b0 + gm) * IN_DIM + c0 + 2 + gc);
    }
    __syncthreads();

    wmma::fragment<wmma::accumulator, 16, 16, 16, float> acc[2][4];
#pragma unroll
    for (int i = 0; i < 2; i++)
#pragma unroll
        for (int j = 0; j < 4; j++) wmma::fill_fragment(acc[i][j], 0.0f);

    for (int it = 0; it < NITER; it++) {
        const bool prod = (it + 1 < NITER);
        const int  nb   = (it + 1) & 1;
        const int  cp   = c0 + 2 * (it + 1);
        const __half* Ab = A[it & 1];
        const __half* Bb = B[it & 1];

        // batch A: issue LDGs for chunks s=0..3 of pair it+1 (latency hidden by MMA)
        float4 v[8];
        if (prod) {
#pragma unroll
            for (int s = 0; s < 4; s++) {
                const float4* s4 = chunk_src(w, tid + s * NTHREADS, cp, ny);
                v[2 * s] = s4[0]; v[2 * s + 1] = s4[1];
            }
        }

        // MMA kk = 0..4
#pragma unroll
        for (int kk = 0; kk < 5; kk++) {
            wmma::fragment<wmma::matrix_a, 16, 16, 16, __half, wmma::row_major> af[2];
            wmma::fragment<wmma::matrix_b, 16, 16, 16, __half, wmma::row_major> bf[4];
#pragma unroll
            for (int i = 0; i < 2; i++)
                wmma::load_matrix_sync(af[i],
                    Ab + (wm * 32 + i * 16) * A_STRIDE + kk * 16, A_STRIDE);
#pragma unroll
            for (int j = 0; j < 4; j++)
                wmma::load_matrix_sync(bf[j],
                    Bb + (kk * 16) * B_STRIDE + wn * 64 + j * 16, B_STRIDE);
#pragma unroll
            for (int i = 0; i < 2; i++)
#pragma unroll
                for (int j = 0; j < 4; j++)
                    wmma::mma_sync(acc[i][j], af[i], bf[j], acc[i][j]);
        }

        // STS batch A, then issue LDGs batch B (s=4..8)
        float4 u[10];
        if (prod) {
#pragma unroll
            for (int s = 0; s < 4; s++)
                chunk_sts(B[nb], tid + s * NTHREADS, v[2 * s], v[2 * s + 1]);
#pragma unroll
            for (int s = 0; s < 5; s++) {
                int j = tid + (s + 4) * NTHREADS;
                if (j < CHUNKS) {
                    const float4* s4 = chunk_src(w, j, cp, ny);
                    u[2 * s] = s4[0]; u[2 * s + 1] = s4[1];
                }
            }
        }

        // MMA kk = 5..8
#pragma unroll
        for (int kk = 5; kk < 9; kk++) {
            wmma::fragment<wmma::matrix_a, 16, 16, 16, __half, wmma::row_major> af[2];
            wmma::fragment<wmma::matrix_b, 16, 16, 16, __half, wmma::row_major> bf[4];
#pragma unroll
            for (int i = 0; i < 2; i++)
                wmma::load_matrix_sync(af[i],
                    Ab + (wm * 32 + i * 16) * A_STRIDE + kk * 16, A_STRIDE);
#pragma unroll
            for (int j = 0; j < 4; j++)
                wmma::load_matrix_sync(bf[j],
                    Bb + (kk * 16) * B_STRIDE + wn * 64 + j * 16, B_STRIDE);
#pragma unroll
            for (int i = 0; i < 2; i++)
#pragma unroll
                for (int j = 0; j < 4; j++)
                    wmma::mma_sync(acc[i][j], af[i], bf[j], acc[i][j]);
        }

        // STS batch B + gen A for pair it+1
        if (prod) {
#pragma unroll
            for (int s = 0; s < 5; s++) {
                int j = tid + (s + 4) * NTHREADS;
                if (j < CHUNKS)
                    chunk_sts(B[nb], j, u[2 * s], u[2 * s + 1]);
            }
            gen_A(A[nb] + gm * A_STRIDE + gc * NROWS, xv, &prevj[nb]);
            if (it + 2 < NITER)
                xv = __ldg(x + (size_t)(b0 + gm) * IN_DIM + c0 + 2 * (it + 2) + gc);
        }
        __syncthreads();   // pair it+1 visible; MMA(it) done before buf reuse
    }

    // epilogue: stage fp32 tile (128x128) in smem, then STG to scratch
    float* stage = (float*)smem;
#pragma unroll
    for (int i = 0; i < 2; i++)
#pragma unroll
        for (int j = 0; j < 4; j++)
            wmma::store_matrix_sync(
                stage + (wm * 32 + i * 16) * NTILE + wn * 64 + j * 16,
                acc[i][j], NTILE, wmma::mem_row_major);
    __syncthreads();

    {
        float* dstb = g_scratch + ((size_t)blockIdx.z * BATCH + b0) * OUT_DIM
                    + ny * NTILE;
        const float4* st4 = (const float4*)stage;
#pragma unroll
        for (int r = 0; r < 16; r++) {
            int q  = r * NTHREADS + tid;      // float4 index in 128x128 tile
            int mm = q >> 5;
            int nn = q & 31;
            ((float4*)(dstb + (size_t)mm * OUT_DIM))[nn] = st4[q];
        }
    }
}

// ---------------- reduce partials: 4 threads/output x 4 z, shfl combine -------
// 131072 threads: 512 blocks x 256. Plain store (no zero kernel needed).
__global__ void __launch_bounds__(256, 1)
reduce_kernel(float4* __restrict__ out)
{
    int g = blockIdx.x * 256 + threadIdx.x;    // 0..131071
    int i = g >> 2;                            // float4 output index (0..32767)
    int h = g & 3;                             // z-quarter
    const float4* s = (const float4*)g_scratch;
    float4 a = make_float4(0.f, 0.f, 0.f, 0.f);
#pragma unroll
    for (int z = 0; z < 4; z++) {
        float4 b = s[(size_t)(h * 4 + z) * (BATCH * OUT_DIM / 4) + i];
        a.x += b.x; a.y += b.y; a.z += b.z; a.w += b.w;
    }
    // combine across the 4 consecutive lanes handling output i
#pragma unroll
    for (int off = 1; off <= 2; off <<= 1) {
        a.x += __shfl_xor_sync(0xffffffffu, a.x, off);
        a.y += __shfl_xor_sync(0xffffffffu, a.y, off);
        a.z += __shfl_xor_sync(0xffffffffu, a.z, off);
        a.w += __shfl_xor_sync(0xffffffffu, a.w, off);
    }
    if (h == 0) out[i] = a;
}

extern "C" void kernel_launch(void* const* d_in, const int* in_sizes, int n_in,
                              void* d_out, int out_size)
{
    const float* x = (const float*)d_in[0];
    const float* w = (const float*)d_in[1];
    float* out = (float*)d_out;

    cudaFuncSetAttribute(kan_wmma_kernel,
                         cudaFuncAttributeMaxDynamicSharedMemorySize, SMEM_TOTAL);

    dim3 grid(BATCH / MT, OUT_DIM / NTILE, ZSPLIT);
    kan_wmma_kernel<<<grid, NTHREADS, SMEM_TOTAL>>>(x, w);

    reduce_kernel<<<512, 256>>>((float4*)out);
}